// round 12
// baseline (speedup 1.0000x reference)
#include <cuda_runtime.h>
#include <math.h>

#define B_ 64
#define T_ 2048
#define I_ 64
#define S_ 128
#define O_ 64
#define LN_EPS 1e-5f
#define TP 2052
#define NSEG 16
#define SEGT 128

typedef unsigned long long ull;

__device__ float g_GX[2ull*B_*TP*S_];
__device__ float g_H [B_*T_*S_];
__device__ float g_xsum[B_*I_];
__device__ float g_boSum[B_*O_];
__device__ float g_boSsq[B_*O_];
__device__ float g_S1, g_S2, g_SA;

__device__ __forceinline__ ull pack2(float lo, float hi) {
    ull r; asm("mov.b64 %0,{%1,%2};" : "=l"(r) : "f"(lo), "f"(hi)); return r;
}
__device__ __forceinline__ void unpack2(ull v, float &lo, float &hi) {
    asm("mov.b64 {%0,%1},%2;" : "=f"(lo), "=f"(hi) : "l"(v));
}
__device__ __forceinline__ ull ffma2(ull a, ull b, ull c) {
    ull d; asm("fma.rn.f32x2 %0,%1,%2,%3;" : "=l"(d) : "l"(a), "l"(b), "l"(c)); return d;
}
__device__ __forceinline__ ull addf2(ull a, ull b) {
    ull r; asm("add.rn.f32x2 %0,%1,%2;" : "=l"(r) : "l"(a), "l"(b)); return r;
}

__global__ void zeroK() {
    int i = blockIdx.x * blockDim.x + threadIdx.x;
    if (i < B_*O_) { g_boSum[i] = 0.f; g_boSsq[i] = 0.f; }
    if (i < B_*I_) g_xsum[i] = 0.f;
    if (i == 0) { g_S1 = 0.f; g_S2 = 0.f; g_SA = 0.f; }
}

// ---------- gateK: fused G+B per thread, 16 tiles/batch ----------
__global__ __launch_bounds__(128) void gateK(
    const float* __restrict__ x, const float* __restrict__ Wsel,
    const float* __restrict__ bsel, const float* __restrict__ Bm)
{
    __shared__ __align__(16) float xs[2][512];
    __shared__ __align__(16) float xred[128];
    int tid = threadIdx.x;
    int s = tid;
    ull w2G[32], w2B[32];
#pragma unroll
    for (int k = 0; k < 32; k++) {
        w2G[k] = pack2(Wsel[s*I_ + 2*k], Wsel[s*I_ + 2*k+1]);
        w2B[k] = pack2(Bm[s*I_ + 2*k],  Bm[s*I_ + 2*k+1]);
    }
    float bias = bsel[s];

    int b = blockIdx.x >> 4;
    int t0 = (blockIdx.x & 15) << 7;
    const float* xseg = x + ((size_t)b*T_ + t0)*I_;
    float2* outp = ((float2*)g_GX) + (size_t)b*TP*S_ + s;
    float xacc = 0.f;
    int ci = tid & 63, r0 = (tid >> 6) * 4;

    ((float4*)xs[0])[tid] = ((const float4*)xseg)[tid];
    __syncthreads();

    for (int st = 0; st < 16; st++) {
        int cur = st & 1;
        bool more = (st < 15);
        float4 rx = make_float4(0.f, 0.f, 0.f, 0.f);
        if (more) rx = ((const float4*)(xseg + (size_t)(st+1)*512))[tid];
        int tb = t0 + st*8;
#pragma unroll
        for (int r = 0; r < 8; r++) {
            const ulonglong2* xv = (const ulonglong2*)(xs[cur] + r*64);
            ull g0=0, g1=0, b0=0, b1=0;
#pragma unroll
            for (int i = 0; i < 16; i += 2) {
                ulonglong2 p = xv[i], q = xv[i+1];
                g0 = ffma2(w2G[2*i+0], p.x, g0); b0 = ffma2(w2B[2*i+0], p.x, b0);
                g1 = ffma2(w2G[2*i+1], p.y, g1); b1 = ffma2(w2B[2*i+1], p.y, b1);
                g0 = ffma2(w2G[2*i+2], q.x, g0); b0 = ffma2(w2B[2*i+2], q.x, b0);
                g1 = ffma2(w2G[2*i+3], q.y, g1); b1 = ffma2(w2B[2*i+3], q.y, b1);
            }
            float u,v,e,f;
            unpack2(g0,u,v); unpack2(g1,e,f);
            float dg = (u+v)+(e+f);
            unpack2(b0,u,v); unpack2(b1,e,f);
            float db = (u+v)+(e+f);
            float gt = 1.f/(1.f + __expf(-(dg + bias)));
            outp[(size_t)(tb + r)*S_] = make_float2(gt, db);
        }
        xacc += (xs[cur][(r0+0)*64 + ci] + xs[cur][(r0+1)*64 + ci])
              + (xs[cur][(r0+2)*64 + ci] + xs[cur][(r0+3)*64 + ci]);
        __syncthreads();
        if (more) ((float4*)xs[cur ^ 1])[tid] = rx;
        __syncthreads();
    }
    xred[tid] = xacc;
    __syncthreads();
    if (tid < 64) atomicAdd(&g_xsum[b*I_ + tid], xred[tid] + xred[tid+64]);
}

__global__ __launch_bounds__(128) void selFin(
    const float* __restrict__ Wsel, const float* __restrict__ bsel)
{
    __shared__ float part[4];
    int tid = threadIdx.x, b = blockIdx.x;
    float acc = bsel[tid];
    const float invT = 1.0f/(float)T_;
    const float* w  = Wsel + tid*I_;
    const float* xm = g_xsum + b*I_;
#pragma unroll 8
    for (int k = 0; k < I_; k++) acc += xm[k]*invT*w[k];
    float sg = 1.f/(1.f + __expf(-acc));
#pragma unroll
    for (int off = 16; off > 0; off >>= 1) sg += __shfl_xor_sync(0xffffffffu, sg, off);
    if ((tid & 31) == 0) part[tid >> 5] = sg;
    __syncthreads();
    if (tid == 0) atomicAdd(&g_SA, (part[0]+part[1]) + (part[2]+part[3]));
}

// ---------- recK: lane-paired halves, 1 barrier/step, packed stat sums ----------
__global__ __launch_bounds__(256, 1) void recK(
    const float* __restrict__ A, const float* __restrict__ gamma,
    const float* __restrict__ beta)
{
    __shared__ __align__(16) float hbuf[2][136];
    __shared__ __align__(16) float2 red[2][16];
    int tid = threadIdx.x, b = blockIdx.x;
    int w = tid >> 5, lane = tid & 31;
    int s = (w << 4) + (lane >> 1);
    int q = lane & 1;
    int hoff = s + ((s & 64) >> 4);
    const float invS = 1.f/(float)S_;

    float gam_s = gamma[s], bet_s = beta[s];
    float gamI = gam_s * invS;
    float agI = 0.f, abv = 0.f;
    {
        const float* ar = A + s*S_;
#pragma unroll 16
        for (int k = 0; k < S_; k++) { agI += ar[k]*gamma[k]; abv += ar[k]*beta[k]; }
        agI *= invS;
    }
    ull a2[32];
    {
        const float* ar = A + s*S_ + q*64;
        const float* gm = gamma + q*64;
#pragma unroll
        for (int k = 0; k < 32; k++)
            a2[k] = pack2(ar[2*k]*gm[2*k], ar[2*k+1]*gm[2*k+1]);
    }

    if (tid < 136) { hbuf[0][tid] = 0.f; hbuf[1][tid] = 0.f; }
    if (tid < 32)  ((float2*)red)[tid] = make_float2(0.f, 0.f);

    const float2* GX = ((const float2*)g_GX) + (size_t)b*TP*S_ + s;
    float* Hp = g_H + (size_t)b*T_*S_ + s;
    float2 gx[4];
#pragma unroll
    for (int j = 0; j < 4; j++) gx[j] = GX[(size_t)j*S_];
    float hbmine = 0.f;
    __syncthreads();

    int p = 0;
#pragma unroll 4
    for (int t = 0; t < T_; t++) {
        float2 gxv = gx[t & 3];
        gx[t & 3] = GX[(size_t)(t + 4)*S_];

        // LN stats of hb_{t-1}: packed (sum,ssq) tree over 16 warp partials
        const ull* rp = (const ull*)red[p];
        ull u0 = addf2(rp[0],  rp[1]),  u1 = addf2(rp[2],  rp[3]);
        ull u2 = addf2(rp[4],  rp[5]),  u3 = addf2(rp[6],  rp[7]);
        ull u4 = addf2(rp[8],  rp[9]),  u5 = addf2(rp[10], rp[11]);
        ull u6 = addf2(rp[12], rp[13]), u7 = addf2(rp[14], rp[15]);
        ull z = addf2(addf2(addf2(u0,u1), addf2(u2,u3)),
                      addf2(addf2(u4,u5), addf2(u6,u7)));
        float sum, ssq; unpack2(z, sum, ssq);
        float mu  = sum * invS;
        float ve  = fmaf(ssq, invS, LN_EPS) - mu*mu;
        float rin = rsqrtf(ve);

        const ulonglong2* hv = (const ulonglong2*)(&hbuf[p][q*68]);
        ull ac0 = 0, ac1 = 0, ac2 = 0, ac3 = 0;
#pragma unroll
        for (int i = 0; i < 16; i += 4) {
            ulonglong2 pv = hv[i], rv = hv[i+1], uv = hv[i+2], vv = hv[i+3];
            ac0 = ffma2(a2[2*i+0], pv.x, ac0); ac1 = ffma2(a2[2*i+1], pv.y, ac1);
            ac2 = ffma2(a2[2*i+2], rv.x, ac2); ac3 = ffma2(a2[2*i+3], rv.y, ac3);
            ac0 = ffma2(a2[2*i+4], uv.x, ac0); ac1 = ffma2(a2[2*i+5], uv.y, ac1);
            ac2 = ffma2(a2[2*i+6], vv.x, ac2); ac3 = ffma2(a2[2*i+7], vv.y, ac3);
        }
        float p0,p1,p2,p3,p4,p5,p6,p7;
        unpack2(ac0,p0,p1); unpack2(ac1,p2,p3); unpack2(ac2,p4,p5); unpack2(ac3,p6,p7);
        float dmine = ((p0+p1)+(p2+p3)) + ((p4+p5)+(p6+p7));
        float dfull = dmine + __shfl_xor_sync(0xffffffffu, dmine, 1);

        float abx  = (t > 0) ? (abv + gxv.y) : gxv.y;
        float preh = hbmine * gam_s;
        float hpn = (t > 0) ? fmaf(fmaf(-sum, gamI, preh), rin, bet_s) : 0.f;
        float nextraw = fmaf(fmaf(-sum, agI, dfull), rin, abx);
        float hb = fmaf(gxv.x, nextraw - hpn, hpn);
        if (t > 0 && !q) Hp[(size_t)(t-1)*S_] = hpn;
        if (!q) hbuf[p ^ 1][hoff] = hb;
        hbmine = hb;

        float s1 = hb, s2 = hb*hb;
#pragma unroll
        for (int off = 16; off > 2; off >>= 1) {
            s1 += __shfl_xor_sync(0xffffffffu, s1, off);
            s2 += __shfl_xor_sync(0xffffffffu, s2, off);
        }
        if ((lane & 0x1D) == 0) red[p ^ 1][2*w + (lane >> 1)] = make_float2(s1, s2);
        __syncthreads();
        p ^= 1;
    }

    {
        const ull* rp = (const ull*)red[p];
        ull u0 = addf2(rp[0],  rp[1]),  u1 = addf2(rp[2],  rp[3]);
        ull u2 = addf2(rp[4],  rp[5]),  u3 = addf2(rp[6],  rp[7]);
        ull u4 = addf2(rp[8],  rp[9]),  u5 = addf2(rp[10], rp[11]);
        ull u6 = addf2(rp[12], rp[13]), u7 = addf2(rp[14], rp[15]);
        ull z = addf2(addf2(addf2(u0,u1), addf2(u2,u3)),
                      addf2(addf2(u4,u5), addf2(u6,u7)));
        float sum, ssq; unpack2(z, sum, ssq);
        float mu  = sum * invS;
        float ve  = fmaf(ssq, invS, LN_EPS) - mu*mu;
        float rin = rsqrtf(ve);
        float hpn = fmaf(fmaf(-sum, gamI, hbmine*gam_s), rin, bet_s);
        if (!q) Hp[(size_t)(T_-1)*S_] = hpn;
    }
}

// ---------- outK: lane-paired outputs, 2 barriers/group, register diffs ----------
__global__ __launch_bounds__(128) void outK(
    const float* __restrict__ x, const float* __restrict__ C,
    const float* __restrict__ D, float* __restrict__ out)
{
    __shared__ __align__(16) float Hs[512];
    __shared__ __align__(16) float xsO[256];
    __shared__ __align__(16) ull  ysq[256];   // per (row, o): packed (y^2, d^2)
    __shared__ __align__(16) float redS[128];

    int tid = threadIdx.x;
    int b = blockIdx.x >> 4, seg = blockIdx.x & 15;
    int o = tid >> 1, q = tid & 1;
    int w = tid >> 5, lane = tid & 31;

    ull c2[32], d2[16];
#pragma unroll
    for (int k = 0; k < 32; k++)
        c2[k] = pack2(C[o*S_ + q*64 + 2*k], C[o*S_ + q*64 + 2*k+1]);
#pragma unroll
    for (int k = 0; k < 16; k++)
        d2[k] = pack2(D[o*I_ + q*32 + 2*k], D[o*I_ + q*32 + 2*k+1]);

    float boS=0.f, boQ=0.f, nrmAcc=0.f, difAcc=0.f, yprev=0.f;
    int t0 = seg << 7;

    if (seg > 0) {
        Hs[tid] = g_H[((size_t)b*T_ + t0 - 1)*S_ + tid];
        if (tid < 64) xsO[tid] = x[((size_t)b*T_ + t0 - 1)*I_ + tid];
        __syncthreads();
        {
            const ull* hv = (const ull*)(Hs + q*64);
            const ull* xv = (const ull*)(xsO + q*32);
            ull a0=0, a1=0;
#pragma unroll
            for (int k = 0; k < 32; k += 2) {
                a0 = ffma2(c2[k], hv[k], a0); a1 = ffma2(c2[k+1], hv[k+1], a1);
            }
#pragma unroll
            for (int k = 0; k < 16; k += 2) {
                a0 = ffma2(d2[k], xv[k], a0); a1 = ffma2(d2[k+1], xv[k+1], a1);
            }
            float u,v,e,f2; unpack2(a0,u,v); unpack2(a1,e,f2);
            float dm = (u+v)+(e+f2);
            yprev = dm + __shfl_xor_sync(0xffffffffu, dm, 1);
        }
        __syncthreads();
    }

    for (int g = 0; g < SEGT/4; g++) {
        int tbase = t0 + (g << 2);
#pragma unroll
        for (int j = 0; j < 4; j++)
            Hs[j*128 + tid] = g_H[((size_t)b*T_ + tbase + j)*S_ + tid];
        xsO[tid]       = x[((size_t)b*T_ + tbase +     (tid >> 6))*I_ + (tid & 63)];
        xsO[tid + 128] = x[((size_t)b*T_ + tbase + 2 + (tid >> 6))*I_ + (tid & 63)];
        __syncthreads();                        // bar 1: tiles ready

        float y[4];
#pragma unroll
        for (int r = 0; r < 4; r++) {
            const ull* hv = (const ull*)(Hs + r*128 + q*64);
            const ull* xv = (const ull*)(xsO + r*64 + q*32);
            ull a0=0, a1=0, a2b=0, a3=0;
#pragma unroll
            for (int k = 0; k < 32; k += 4) {
                a0  = ffma2(c2[k],   hv[k],   a0);
                a1  = ffma2(c2[k+1], hv[k+1], a1);
                a2b = ffma2(c2[k+2], hv[k+2], a2b);
                a3  = ffma2(c2[k+3], hv[k+3], a3);
            }
#pragma unroll
            for (int k = 0; k < 16; k += 4) {
                a0  = ffma2(d2[k],   xv[k],   a0);
                a1  = ffma2(d2[k+1], xv[k+1], a1);
                a2b = ffma2(d2[k+2], xv[k+2], a2b);
                a3  = ffma2(d2[k+3], xv[k+3], a3);
            }
            float u,v,e,f2,m,n,pp,qq;
            unpack2(a0,u,v); unpack2(a1,e,f2); unpack2(a2b,m,n); unpack2(a3,pp,qq);
            float dm = ((u+v)+(e+f2)) + ((m+n)+(pp+qq));
            y[r] = dm + __shfl_xor_sync(0xffffffffu, dm, 1);
        }
        float d0 = y[0] - yprev;
        if (seg == 0 && g == 0) d0 = 0.f;
        float dd[4] = { d0, y[1]-y[0], y[2]-y[1], y[3]-y[2] };
        yprev = y[3];
#pragma unroll
        for (int r = 0; r < 4; r++) {
            boS += y[r]; boQ += y[r]*y[r];
            if (q == 0) ysq[r*64 + o] = pack2(y[r]*y[r], dd[r]*dd[r]);
        }
        if (q == 0 && tbase + 3 == T_ - 1) out[b*O_ + o] = y[3];
        __syncthreads();                        // bar 2: ysq ready

        {   // warp w reduces row w: packed (sum y^2, sum d^2)
            ull v = addf2(ysq[w*64 + lane], ysq[w*64 + 32 + lane]);
#pragma unroll
            for (int off = 16; off > 0; off >>= 1)
                v = addf2(v, __shfl_xor_sync(0xffffffffu, v, off));
            if (lane == 0) {
                float sy, sd; unpack2(v, sy, sd);
                nrmAcc += sqrtf(sy);
                difAcc += sqrtf(sd);
            }
        }
    }

    if (lane == 0) { atomicAdd(&g_S2, nrmAcc); atomicAdd(&g_S1, difAcc); }
    if (q == 0) {
        atomicAdd(&g_boSum[b*O_ + o], boS);
        atomicAdd(&g_boSsq[b*O_ + o], boQ);
    }
    (void)redS;
}

__global__ void finK(float* __restrict__ out)
{
    __shared__ float part[8];
    int tid = threadIdx.x;
    float acc = 0.f;
    for (int idx = tid; idx < B_*O_; idx += 256) {
        float sum = g_boSum[idx], ssq = g_boSsq[idx];
        float var = (ssq - sum*sum*(1.f/T_)) * (1.f/(T_ - 1));
        acc += sqrtf(fmaxf(var, 0.f));
    }
#pragma unroll
    for (int off = 16; off > 0; off >>= 1) acc += __shfl_xor_sync(0xffffffffu, acc, off);
    if ((tid & 31) == 0) part[tid >> 5] = acc;
    __syncthreads();
    if (tid == 0) {
        float tot = 0.f;
#pragma unroll
        for (int k = 0; k < 8; k++) tot += part[k];
        out[4096] = 1.f / (1.f + g_S1 / (float)(B_*(T_-1)));
        out[4097] = g_S2 / (float)(B_*T_);
        out[4098] = g_SA / (float)(B_*S_);
        out[4099] = tot  / (float)(B_*O_);
    }
}

extern "C" void kernel_launch(void* const* d_in, const int* in_sizes, int n_in,
                              void* d_out, int out_size)
{
    const float* x     = (const float*)d_in[0];
    const float* A     = (const float*)d_in[1];
    const float* Bm    = (const float*)d_in[2];
    const float* C     = (const float*)d_in[3];
    const float* D     = (const float*)d_in[4];
    const float* Wsel  = (const float*)d_in[5];
    const float* bsel  = (const float*)d_in[6];
    const float* gamma = (const float*)d_in[7];
    const float* beta  = (const float*)d_in[8];
    float* out = (float*)d_out;

    zeroK<<<16, 256>>>();
    gateK<<<B_*16, 128>>>(x, Wsel, bsel, Bm);
    recK<<<B_, 256>>>(A, gamma, beta);
    outK<<<B_*NSEG, 128>>>(x, C, D, out);   // profiled slot
    selFin<<<B_, 128>>>(Wsel, bsel);
    finK<<<1, 256>>>(out);
}

// round 13
// speedup vs baseline: 1.0651x; 1.0651x over previous
#include <cuda_runtime.h>
#include <math.h>

#define B_ 64
#define T_ 2048
#define I_ 64
#define S_ 128
#define O_ 64
#define LN_EPS 1e-5f
#define TP 2052
#define NSEG 16
#define SEGT 128

typedef unsigned long long ull;

__device__ float g_GX[2ull*B_*TP*S_];
__device__ float g_H [B_*T_*S_];
__device__ float g_xsum[B_*I_];
__device__ float g_boSum[B_*O_];
__device__ float g_boSsq[B_*O_];
__device__ float g_S1, g_S2, g_SA;

__device__ __forceinline__ ull pack2(float lo, float hi) {
    ull r; asm("mov.b64 %0,{%1,%2};" : "=l"(r) : "f"(lo), "f"(hi)); return r;
}
__device__ __forceinline__ void unpack2(ull v, float &lo, float &hi) {
    asm("mov.b64 {%0,%1},%2;" : "=f"(lo), "=f"(hi) : "l"(v));
}
__device__ __forceinline__ ull ffma2(ull a, ull b, ull c) {
    ull d; asm("fma.rn.f32x2 %0,%1,%2,%3;" : "=l"(d) : "l"(a), "l"(b), "l"(c)); return d;
}
__device__ __forceinline__ ull addf2(ull a, ull b) {
    ull r; asm("add.rn.f32x2 %0,%1,%2;" : "=l"(r) : "l"(a), "l"(b)); return r;
}

__global__ void zeroK() {
    int i = blockIdx.x * blockDim.x + threadIdx.x;
    if (i < B_*O_) { g_boSum[i] = 0.f; g_boSsq[i] = 0.f; }
    if (i < B_*I_) g_xsum[i] = 0.f;
    if (i == 0) { g_S1 = 0.f; g_S2 = 0.f; g_SA = 0.f; }
}

// ---------- gateK: fused G+B per thread, 16 tiles/batch ----------
__global__ __launch_bounds__(128) void gateK(
    const float* __restrict__ x, const float* __restrict__ Wsel,
    const float* __restrict__ bsel, const float* __restrict__ Bm)
{
    __shared__ __align__(16) float xs[2][512];
    __shared__ __align__(16) float xred[128];
    int tid = threadIdx.x;
    int s = tid;
    ull w2G[32], w2B[32];
#pragma unroll
    for (int k = 0; k < 32; k++) {
        w2G[k] = pack2(Wsel[s*I_ + 2*k], Wsel[s*I_ + 2*k+1]);
        w2B[k] = pack2(Bm[s*I_ + 2*k],  Bm[s*I_ + 2*k+1]);
    }
    float bias = bsel[s];

    int b = blockIdx.x >> 4;
    int t0 = (blockIdx.x & 15) << 7;
    const float* xseg = x + ((size_t)b*T_ + t0)*I_;
    float2* outp = ((float2*)g_GX) + (size_t)b*TP*S_ + s;
    float xacc = 0.f;
    int ci = tid & 63, r0 = (tid >> 6) * 4;

    ((float4*)xs[0])[tid] = ((const float4*)xseg)[tid];
    __syncthreads();

    for (int st = 0; st < 16; st++) {
        int cur = st & 1;
        bool more = (st < 15);
        float4 rx = make_float4(0.f, 0.f, 0.f, 0.f);
        if (more) rx = ((const float4*)(xseg + (size_t)(st+1)*512))[tid];
        int tb = t0 + st*8;
#pragma unroll
        for (int r = 0; r < 8; r++) {
            const ulonglong2* xv = (const ulonglong2*)(xs[cur] + r*64);
            ull g0=0, g1=0, b0=0, b1=0;
#pragma unroll
            for (int i = 0; i < 16; i += 2) {
                ulonglong2 p = xv[i], q = xv[i+1];
                g0 = ffma2(w2G[2*i+0], p.x, g0); b0 = ffma2(w2B[2*i+0], p.x, b0);
                g1 = ffma2(w2G[2*i+1], p.y, g1); b1 = ffma2(w2B[2*i+1], p.y, b1);
                g0 = ffma2(w2G[2*i+2], q.x, g0); b0 = ffma2(w2B[2*i+2], q.x, b0);
                g1 = ffma2(w2G[2*i+3], q.y, g1); b1 = ffma2(w2B[2*i+3], q.y, b1);
            }
            float u,v,e,f;
            unpack2(g0,u,v); unpack2(g1,e,f);
            float dg = (u+v)+(e+f);
            unpack2(b0,u,v); unpack2(b1,e,f);
            float db = (u+v)+(e+f);
            float gt = 1.f/(1.f + __expf(-(dg + bias)));
            outp[(size_t)(tb + r)*S_] = make_float2(gt, db);
        }
        xacc += (xs[cur][(r0+0)*64 + ci] + xs[cur][(r0+1)*64 + ci])
              + (xs[cur][(r0+2)*64 + ci] + xs[cur][(r0+3)*64 + ci]);
        __syncthreads();
        if (more) ((float4*)xs[cur ^ 1])[tid] = rx;
        __syncthreads();
    }
    xred[tid] = xacc;
    __syncthreads();
    if (tid < 64) atomicAdd(&g_xsum[b*I_ + tid], xred[tid] + xred[tid+64]);
}

__global__ __launch_bounds__(128) void selFin(
    const float* __restrict__ Wsel, const float* __restrict__ bsel)
{
    __shared__ float part[4];
    int tid = threadIdx.x, b = blockIdx.x;
    float acc = bsel[tid];
    const float invT = 1.0f/(float)T_;
    const float* w  = Wsel + tid*I_;
    const float* xm = g_xsum + b*I_;
#pragma unroll 8
    for (int k = 0; k < I_; k++) acc += xm[k]*invT*w[k];
    float sg = 1.f/(1.f + __expf(-acc));
#pragma unroll
    for (int off = 16; off > 0; off >>= 1) sg += __shfl_xor_sync(0xffffffffu, sg, off);
    if ((tid & 31) == 0) part[tid >> 5] = sg;
    __syncthreads();
    if (tid == 0) atomicAdd(&g_SA, (part[0]+part[1]) + (part[2]+part[3]));
}

// ---------- recK: lane-paired halves, 1 barrier/step, packed stat sums ----------
__global__ __launch_bounds__(256, 1) void recK(
    const float* __restrict__ A, const float* __restrict__ gamma,
    const float* __restrict__ beta)
{
    __shared__ __align__(16) float hbuf[2][136];
    __shared__ __align__(16) float2 red[2][16];
    int tid = threadIdx.x, b = blockIdx.x;
    int w = tid >> 5, lane = tid & 31;
    int s = (w << 4) + (lane >> 1);
    int q = lane & 1;
    int hoff = s + ((s & 64) >> 4);
    const float invS = 1.f/(float)S_;

    float gam_s = gamma[s], bet_s = beta[s];
    float gamI = gam_s * invS;
    float agI = 0.f, abv = 0.f;
    {
        const float* ar = A + s*S_;
#pragma unroll 16
        for (int k = 0; k < S_; k++) { agI += ar[k]*gamma[k]; abv += ar[k]*beta[k]; }
        agI *= invS;
    }
    ull a2[32];
    {
        const float* ar = A + s*S_ + q*64;
        const float* gm = gamma + q*64;
#pragma unroll
        for (int k = 0; k < 32; k++)
            a2[k] = pack2(ar[2*k]*gm[2*k], ar[2*k+1]*gm[2*k+1]);
    }

    if (tid < 136) { hbuf[0][tid] = 0.f; hbuf[1][tid] = 0.f; }
    if (tid < 32)  ((float2*)red)[tid] = make_float2(0.f, 0.f);

    const float2* GX = ((const float2*)g_GX) + (size_t)b*TP*S_ + s;
    float* Hp = g_H + (size_t)b*T_*S_ + s;
    float2 gx[4];
#pragma unroll
    for (int j = 0; j < 4; j++) gx[j] = GX[(size_t)j*S_];
    float hbmine = 0.f;
    __syncthreads();

    int p = 0;
#pragma unroll 4
    for (int t = 0; t < T_; t++) {
        float2 gxv = gx[t & 3];
        gx[t & 3] = GX[(size_t)(t + 4)*S_];

        const ull* rp = (const ull*)red[p];
        ull u0 = addf2(rp[0],  rp[1]),  u1 = addf2(rp[2],  rp[3]);
        ull u2 = addf2(rp[4],  rp[5]),  u3 = addf2(rp[6],  rp[7]);
        ull u4 = addf2(rp[8],  rp[9]),  u5 = addf2(rp[10], rp[11]);
        ull u6 = addf2(rp[12], rp[13]), u7 = addf2(rp[14], rp[15]);
        ull z = addf2(addf2(addf2(u0,u1), addf2(u2,u3)),
                      addf2(addf2(u4,u5), addf2(u6,u7)));
        float sum, ssq; unpack2(z, sum, ssq);
        float mu  = sum * invS;
        float ve  = fmaf(ssq, invS, LN_EPS) - mu*mu;
        float rin = rsqrtf(ve);

        const ulonglong2* hv = (const ulonglong2*)(&hbuf[p][q*68]);
        ull ac0 = 0, ac1 = 0, ac2 = 0, ac3 = 0;
#pragma unroll
        for (int i = 0; i < 16; i += 4) {
            ulonglong2 pv = hv[i], rv = hv[i+1], uv = hv[i+2], vv = hv[i+3];
            ac0 = ffma2(a2[2*i+0], pv.x, ac0); ac1 = ffma2(a2[2*i+1], pv.y, ac1);
            ac2 = ffma2(a2[2*i+2], rv.x, ac2); ac3 = ffma2(a2[2*i+3], rv.y, ac3);
            ac0 = ffma2(a2[2*i+4], uv.x, ac0); ac1 = ffma2(a2[2*i+5], uv.y, ac1);
            ac2 = ffma2(a2[2*i+6], vv.x, ac2); ac3 = ffma2(a2[2*i+7], vv.y, ac3);
        }
        float p0,p1,p2,p3,p4,p5,p6,p7;
        unpack2(ac0,p0,p1); unpack2(ac1,p2,p3); unpack2(ac2,p4,p5); unpack2(ac3,p6,p7);
        float dmine = ((p0+p1)+(p2+p3)) + ((p4+p5)+(p6+p7));
        float dfull = dmine + __shfl_xor_sync(0xffffffffu, dmine, 1);

        float abx  = (t > 0) ? (abv + gxv.y) : gxv.y;
        float preh = hbmine * gam_s;
        float hpn = (t > 0) ? fmaf(fmaf(-sum, gamI, preh), rin, bet_s) : 0.f;
        float nextraw = fmaf(fmaf(-sum, agI, dfull), rin, abx);
        float hb = fmaf(gxv.x, nextraw - hpn, hpn);
        if (t > 0 && !q) Hp[(size_t)(t-1)*S_] = hpn;
        if (!q) hbuf[p ^ 1][hoff] = hb;
        hbmine = hb;

        float s1 = hb, s2 = hb*hb;
#pragma unroll
        for (int off = 16; off > 2; off >>= 1) {
            s1 += __shfl_xor_sync(0xffffffffu, s1, off);
            s2 += __shfl_xor_sync(0xffffffffu, s2, off);
        }
        if ((lane & 0x1D) == 0) red[p ^ 1][2*w + (lane >> 1)] = make_float2(s1, s2);
        __syncthreads();
        p ^= 1;
    }

    {
        const ull* rp = (const ull*)red[p];
        ull u0 = addf2(rp[0],  rp[1]),  u1 = addf2(rp[2],  rp[3]);
        ull u2 = addf2(rp[4],  rp[5]),  u3 = addf2(rp[6],  rp[7]);
        ull u4 = addf2(rp[8],  rp[9]),  u5 = addf2(rp[10], rp[11]);
        ull u6 = addf2(rp[12], rp[13]), u7 = addf2(rp[14], rp[15]);
        ull z = addf2(addf2(addf2(u0,u1), addf2(u2,u3)),
                      addf2(addf2(u4,u5), addf2(u6,u7)));
        float sum, ssq; unpack2(z, sum, ssq);
        float mu  = sum * invS;
        float ve  = fmaf(ssq, invS, LN_EPS) - mu*mu;
        float rin = rsqrtf(ve);
        float hpn = fmaf(fmaf(-sum, gamI, hbmine*gam_s), rin, bet_s);
        if (!q) Hp[(size_t)(T_-1)*S_] = hpn;
    }
}

// ---------- outK: hf-split (R11) + register double-buffer prefetch ----------
__global__ __launch_bounds__(128) void outK(
    const float* __restrict__ x, const float* __restrict__ C,
    const float* __restrict__ D, float* __restrict__ out)
{
    __shared__ __align__(16) float Hs[512];
    __shared__ __align__(16) float xsO[256];
    __shared__ __align__(16) float Ysf[4][64];
    __shared__ __align__(16) float Ys2f[4][64];
    __shared__ __align__(16) float ypS[64];

    int tid = threadIdx.x;
    int b = blockIdx.x >> 4, seg = blockIdx.x & 15;
    int o = tid & 63, hf = tid >> 6;
    int w = tid >> 5, lane = tid & 31;

    ull c2[32], d2[16];
#pragma unroll
    for (int k = 0; k < 32; k++)
        c2[k] = pack2(C[o*S_ + hf*64 + 2*k], C[o*S_ + hf*64 + 2*k+1]);
#pragma unroll
    for (int k = 0; k < 16; k++)
        d2[k] = pack2(D[o*I_ + hf*32 + 2*k], D[o*I_ + hf*32 + 2*k+1]);
    float* dsth = hf ? &Ys2f[0][0] : &Ysf[0][0];
    float boS=0.f, boQ=0.f, nrmAcc=0.f, difAcc=0.f, ylastR=0.f;
    int t0 = seg << 7;

    const float* Hb = g_H + (size_t)b*T_*S_;
    const float* xb = x + (size_t)b*T_*I_;

    if (seg > 0) {
        Hs[tid] = Hb[(size_t)(t0-1)*S_ + tid];
        if (tid < 64) xsO[tid] = xb[(size_t)(t0-1)*I_ + tid];
        __syncthreads();
        {
            const ull* hv = (const ull*)(Hs + hf*64);
            const ull* xv = (const ull*)(xsO + hf*32);
            ull a0=0, a1=0;
#pragma unroll
            for (int k = 0; k < 32; k += 2) {
                a0 = ffma2(c2[k], hv[k], a0); a1 = ffma2(c2[k+1], hv[k+1], a1);
            }
#pragma unroll
            for (int k = 0; k < 16; k += 2) {
                a0 = ffma2(d2[k], xv[k], a0); a1 = ffma2(d2[k+1], xv[k+1], a1);
            }
            float u,v,e,f2; unpack2(a0,u,v); unpack2(a1,e,f2);
            dsth[o] = (u+v)+(e+f2);
        }
        __syncthreads();
        if (tid < 64) ylastR = Ysf[0][tid] + Ys2f[0][tid];
    }

    // prefetch group 0 into registers
    float pH[4], px0, px1;
#pragma unroll
    for (int j = 0; j < 4; j++) pH[j] = Hb[(size_t)(t0 + j)*S_ + tid];
    px0 = xb[(size_t)(t0 +     (tid >> 6))*I_ + o];
    px1 = xb[(size_t)(t0 + 2 + (tid >> 6))*I_ + o];

    for (int g = 0; g < SEGT/4; g++) {
        int tbase = t0 + (g << 2);
        __syncthreads();                            // A: smem consumed
        if (tid < 64) ypS[tid] = ylastR;
#pragma unroll
        for (int j = 0; j < 4; j++) Hs[j*128 + tid] = pH[j];
        xsO[tid]       = px0;
        xsO[tid + 128] = px1;
        __syncthreads();                            // B: tiles staged

        if (g + 1 < SEGT/4) {                       // prefetch next group (overlaps compute)
            int tn = tbase + 4;
#pragma unroll
            for (int j = 0; j < 4; j++) pH[j] = Hb[(size_t)(tn + j)*S_ + tid];
            px0 = xb[(size_t)(tn +     (tid >> 6))*I_ + o];
            px1 = xb[(size_t)(tn + 2 + (tid >> 6))*I_ + o];
        }
#pragma unroll
        for (int r = 0; r < 4; r++) {
            const ull* hv = (const ull*)(Hs + r*128 + hf*64);
            const ull* xv = (const ull*)(xsO + r*64 + hf*32);
            ull a0=0, a1=0, a2b=0, a3=0;
#pragma unroll
            for (int k = 0; k < 32; k += 4) {
                a0  = ffma2(c2[k],   hv[k],   a0);
                a1  = ffma2(c2[k+1], hv[k+1], a1);
                a2b = ffma2(c2[k+2], hv[k+2], a2b);
                a3  = ffma2(c2[k+3], hv[k+3], a3);
            }
#pragma unroll
            for (int k = 0; k < 16; k += 4) {
                a0  = ffma2(d2[k],   xv[k],   a0);
                a1  = ffma2(d2[k+1], xv[k+1], a1);
                a2b = ffma2(d2[k+2], xv[k+2], a2b);
                a3  = ffma2(d2[k+3], xv[k+3], a3);
            }
            float u,v,e,f2,m,n,pp,qq;
            unpack2(a0,u,v); unpack2(a1,e,f2); unpack2(a2b,m,n); unpack2(a3,pp,qq);
            dsth[r*64 + o] = ((u+v)+(e+f2)) + ((m+n)+(pp+qq));
        }
        __syncthreads();                            // C: halves ready
#pragma unroll
        for (int rr = 0; rr < 2; rr++) {
            int r = hf + rr*2;
            float y = Ysf[r][o] + Ys2f[r][o];
            Ysf[r][o] = y;
            boS += y; boQ += y*y;
            if (tbase + r == T_-1) out[b*O_ + o] = y;
        }
        __syncthreads();                            // D: Y combined
        {
            float y0 = Ysf[w][lane], y1 = Ysf[w][lane+32];
            float p0, p1;
            if (w == 0) { p0 = ypS[lane]; p1 = ypS[lane+32]; }
            else        { p0 = Ysf[w-1][lane]; p1 = Ysf[w-1][lane+32]; }
            float sn = y0*y0 + y1*y1;
            float d0 = y0 - p0, d1 = y1 - p1;
            float dn = d0*d0 + d1*d1;
#pragma unroll
            for (int off = 16; off > 0; off >>= 1) {
                sn += __shfl_xor_sync(0xffffffffu, sn, off);
                dn += __shfl_xor_sync(0xffffffffu, dn, off);
            }
            if (lane == 0) {
                nrmAcc += sqrtf(sn);
                if (tbase + w > 0) difAcc += sqrtf(dn);
            }
            if (tid < 64) ylastR = Ysf[3][tid];
        }
    }

    if (lane == 0) { atomicAdd(&g_S2, nrmAcc); atomicAdd(&g_S1, difAcc); }
    __syncthreads();
    Hs[tid] = boS;
    __syncthreads();
    if (tid < 64) atomicAdd(&g_boSum[b*O_ + tid], Hs[tid] + Hs[tid+64]);
    __syncthreads();
    Hs[tid] = boQ;
    __syncthreads();
    if (tid < 64) atomicAdd(&g_boSsq[b*O_ + tid], Hs[tid] + Hs[tid+64]);
}

__global__ void finK(float* __restrict__ out)
{
    __shared__ float part[8];
    int tid = threadIdx.x;
    float acc = 0.f;
    for (int idx = tid; idx < B_*O_; idx += 256) {
        float sum = g_boSum[idx], ssq = g_boSsq[idx];
        float var = (ssq - sum*sum*(1.f/T_)) * (1.f/(T_ - 1));
        acc += sqrtf(fmaxf(var, 0.f));
    }
#pragma unroll
    for (int off = 16; off > 0; off >>= 1) acc += __shfl_xor_sync(0xffffffffu, acc, off);
    if ((tid & 31) == 0) part[tid >> 5] = acc;
    __syncthreads();
    if (tid == 0) {
        float tot = 0.f;
#pragma unroll
        for (int k = 0; k < 8; k++) tot += part[k];
        out[4096] = 1.f / (1.f + g_S1 / (float)(B_*(T_-1)));
        out[4097] = g_S2 / (float)(B_*T_);
        out[4098] = g_SA / (float)(B_*S_);
        out[4099] = tot  / (float)(B_*O_);
    }
}

extern "C" void kernel_launch(void* const* d_in, const int* in_sizes, int n_in,
                              void* d_out, int out_size)
{
    const float* x     = (const float*)d_in[0];
    const float* A     = (const float*)d_in[1];
    const float* Bm    = (const float*)d_in[2];
    const float* C     = (const float*)d_in[3];
    const float* D     = (const float*)d_in[4];
    const float* Wsel  = (const float*)d_in[5];
    const float* bsel  = (const float*)d_in[6];
    const float* gamma = (const float*)d_in[7];
    const float* beta  = (const float*)d_in[8];
    float* out = (float*)d_out;

    zeroK<<<16, 256>>>();
    gateK<<<B_*16, 128>>>(x, Wsel, bsel, Bm);
    recK<<<B_, 256>>>(A, gamma, beta);
    outK<<<B_*NSEG, 128>>>(x, C, D, out);   // profiled slot
    selFin<<<B_, 128>>>(Wsel, bsel);
    finK<<<1, 256>>>(out);
}

// round 14
// speedup vs baseline: 1.1130x; 1.0450x over previous
#include <cuda_runtime.h>
#include <math.h>

#define B_ 64
#define T_ 2048
#define I_ 64
#define S_ 128
#define O_ 64
#define LN_EPS 1e-5f
#define TP 2052
#define NSEG 16
#define SEGT 128

typedef unsigned long long ull;

__device__ float g_GX[2ull*B_*TP*S_];
__device__ float g_H [B_*T_*S_];
__device__ float g_xsum[B_*I_];
__device__ float g_boSum[B_*O_];
__device__ float g_boSsq[B_*O_];
__device__ float g_S1, g_S2, g_SA;

__device__ __forceinline__ ull pack2(float lo, float hi) {
    ull r; asm("mov.b64 %0,{%1,%2};" : "=l"(r) : "f"(lo), "f"(hi)); return r;
}
__device__ __forceinline__ void unpack2(ull v, float &lo, float &hi) {
    asm("mov.b64 {%0,%1},%2;" : "=f"(lo), "=f"(hi) : "l"(v));
}
__device__ __forceinline__ ull ffma2(ull a, ull b, ull c) {
    ull d; asm("fma.rn.f32x2 %0,%1,%2,%3;" : "=l"(d) : "l"(a), "l"(b), "l"(c)); return d;
}

__global__ void zeroA() {
    int i = blockIdx.x * blockDim.x + threadIdx.x;
    if (i < B_*O_) { g_boSum[i] = 0.f; g_boSsq[i] = 0.f; }
}
__global__ void zeroB() {
    int i = blockIdx.x * blockDim.x + threadIdx.x;
    if (i < B_*I_) g_xsum[i] = 0.f;
    if (i == 0) { g_S1 = 0.f; g_S2 = 0.f; g_SA = 0.f; }
}

// ---------- gateK: fused G+B per thread, 8 tiles/batch (R11, measured 170us) ----------
__global__ __launch_bounds__(128) void gateK(
    const float* __restrict__ x, const float* __restrict__ Wsel,
    const float* __restrict__ bsel, const float* __restrict__ Bm)
{
    __shared__ __align__(16) float xs[2][512];
    __shared__ __align__(16) float xred[128];
    int tid = threadIdx.x;
    int s = tid;
    ull w2G[32], w2B[32];
#pragma unroll
    for (int k = 0; k < 32; k++) {
        w2G[k] = pack2(Wsel[s*I_ + 2*k], Wsel[s*I_ + 2*k+1]);
        w2B[k] = pack2(Bm[s*I_ + 2*k],  Bm[s*I_ + 2*k+1]);
    }
    float bias = bsel[s];

    int b = blockIdx.x >> 3;
    int t0 = (blockIdx.x & 7) << 8;
    const float* xseg = x + ((size_t)b*T_ + t0)*I_;
    float2* outp = ((float2*)g_GX) + (size_t)b*TP*S_ + s;
    float xacc = 0.f;
    int ci = tid & 63, r0 = (tid >> 6) * 4;

    ((float4*)xs[0])[tid] = ((const float4*)xseg)[tid];
    __syncthreads();

    for (int st = 0; st < 32; st++) {
        int cur = st & 1;
        bool more = (st < 31);
        float4 rx = make_float4(0.f, 0.f, 0.f, 0.f);
        if (more) rx = ((const float4*)(xseg + (size_t)(st+1)*512))[tid];
        int tb = t0 + st*8;
#pragma unroll
        for (int r = 0; r < 8; r++) {
            const ulonglong2* xv = (const ulonglong2*)(xs[cur] + r*64);
            ull g0=0, g1=0, b0=0, b1=0;
#pragma unroll
            for (int i = 0; i < 16; i += 2) {
                ulonglong2 p = xv[i], q = xv[i+1];
                g0 = ffma2(w2G[2*i+0], p.x, g0); b0 = ffma2(w2B[2*i+0], p.x, b0);
                g1 = ffma2(w2G[2*i+1], p.y, g1); b1 = ffma2(w2B[2*i+1], p.y, b1);
                g0 = ffma2(w2G[2*i+2], q.x, g0); b0 = ffma2(w2B[2*i+2], q.x, b0);
                g1 = ffma2(w2G[2*i+3], q.y, g1); b1 = ffma2(w2B[2*i+3], q.y, b1);
            }
            float u,v,e,f;
            unpack2(g0,u,v); unpack2(g1,e,f);
            float dg = (u+v)+(e+f);
            unpack2(b0,u,v); unpack2(b1,e,f);
            float db = (u+v)+(e+f);
            float gt = 1.f/(1.f + __expf(-(dg + bias)));
            outp[(size_t)(tb + r)*S_] = make_float2(gt, db);
        }
        xacc += (xs[cur][(r0+0)*64 + ci] + xs[cur][(r0+1)*64 + ci])
              + (xs[cur][(r0+2)*64 + ci] + xs[cur][(r0+3)*64 + ci]);
        __syncthreads();
        if (more) ((float4*)xs[cur ^ 1])[tid] = rx;
        __syncthreads();
    }
    xred[tid] = xacc;
    __syncthreads();
    if (tid < 64) atomicAdd(&g_xsum[b*I_ + tid], xred[tid] + xred[tid+64]);
}

__global__ __launch_bounds__(128) void selFin(
    const float* __restrict__ Wsel, const float* __restrict__ bsel)
{
    __shared__ float part[4];
    int tid = threadIdx.x, b = blockIdx.x;
    float acc = bsel[tid];
    const float invT = 1.0f/(float)T_;
    const float* w  = Wsel + tid*I_;
    const float* xm = g_xsum + b*I_;
#pragma unroll 8
    for (int k = 0; k < I_; k++) acc += xm[k]*invT*w[k];
    float sg = 1.f/(1.f + __expf(-acc));
#pragma unroll
    for (int off = 16; off > 0; off >>= 1) sg += __shfl_xor_sync(0xffffffffu, sg, off);
    if ((tid & 31) == 0) part[tid >> 5] = sg;
    __syncthreads();
    if (tid == 0) atomicAdd(&g_SA, (part[0]+part[1]) + (part[2]+part[3]));
}

// ---------- recK: R11 variant (lane-paired halves, 1 barrier/step, 3-level tree) ----------
__global__ __launch_bounds__(256, 1) void recK(
    const float* __restrict__ A, const float* __restrict__ gamma,
    const float* __restrict__ beta)
{
    __shared__ __align__(16) float hbuf[2][136];
    __shared__ __align__(16) float2 red[2][16];
    int tid = threadIdx.x, b = blockIdx.x;
    int w = tid >> 5, lane = tid & 31;
    int s = (w << 4) + (lane >> 1);
    int q = lane & 1;
    int hoff = s + ((s & 64) >> 4);
    const float invS = 1.f/(float)S_;

    float gam_s = gamma[s], bet_s = beta[s];
    float gamI = gam_s * invS;
    float agI = 0.f, abv = 0.f;
    {
        const float* ar = A + s*S_;
#pragma unroll 16
        for (int k = 0; k < S_; k++) { agI += ar[k]*gamma[k]; abv += ar[k]*beta[k]; }
        agI *= invS;
    }
    ull a2[32];
    {
        const float* ar = A + s*S_ + q*64;
        const float* gm = gamma + q*64;
#pragma unroll
        for (int k = 0; k < 32; k++)
            a2[k] = pack2(ar[2*k]*gm[2*k], ar[2*k+1]*gm[2*k+1]);
    }

    if (tid < 136) { hbuf[0][tid] = 0.f; hbuf[1][tid] = 0.f; }
    if (tid < 32)  ((float2*)red)[tid] = make_float2(0.f, 0.f);

    const float2* GX = ((const float2*)g_GX) + (size_t)b*TP*S_ + s;
    float* Hp = g_H + (size_t)b*T_*S_ + s;
    float2 gx[4];
#pragma unroll
    for (int j = 0; j < 4; j++) gx[j] = GX[(size_t)j*S_];
    float hbmine = 0.f;
    __syncthreads();

    int p = 0;
#pragma unroll 4
    for (int t = 0; t < T_; t++) {
        float2 gxv = gx[t & 3];
        gx[t & 3] = GX[(size_t)(t + 4)*S_];

        const float4* rp = (const float4*)red[p];
        float4 r0 = rp[0], r1 = rp[1], r2 = rp[2], r3 = rp[3];
        float4 r4 = rp[4], r5 = rp[5], r6 = rp[6], r7 = rp[7];
        float sum = (((r0.x + r0.z) + (r1.x + r1.z)) + ((r2.x + r2.z) + (r3.x + r3.z)))
                  + (((r4.x + r4.z) + (r5.x + r5.z)) + ((r6.x + r6.z) + (r7.x + r7.z)));
        float ssq = (((r0.y + r0.w) + (r1.y + r1.w)) + ((r2.y + r2.w) + (r3.y + r3.w)))
                  + (((r4.y + r4.w) + (r5.y + r5.w)) + ((r6.y + r6.w) + (r7.y + r7.w)));
        float mu  = sum * invS;
        float ve  = fmaf(ssq, invS, LN_EPS) - mu*mu;
        float rin = rsqrtf(ve);

        const ulonglong2* hv = (const ulonglong2*)(&hbuf[p][q*68]);
        ull ac0 = 0, ac1 = 0, ac2 = 0, ac3 = 0;
#pragma unroll
        for (int i = 0; i < 16; i += 4) {
            ulonglong2 pv = hv[i], rv = hv[i+1], uv = hv[i+2], vv = hv[i+3];
            ac0 = ffma2(a2[2*i+0], pv.x, ac0); ac1 = ffma2(a2[2*i+1], pv.y, ac1);
            ac2 = ffma2(a2[2*i+2], rv.x, ac2); ac3 = ffma2(a2[2*i+3], rv.y, ac3);
            ac0 = ffma2(a2[2*i+4], uv.x, ac0); ac1 = ffma2(a2[2*i+5], uv.y, ac1);
            ac2 = ffma2(a2[2*i+6], vv.x, ac2); ac3 = ffma2(a2[2*i+7], vv.y, ac3);
        }
        float p0,p1,p2,p3,p4,p5,p6,p7;
        unpack2(ac0,p0,p1); unpack2(ac1,p2,p3); unpack2(ac2,p4,p5); unpack2(ac3,p6,p7);
        float dmine = ((p0+p1)+(p2+p3)) + ((p4+p5)+(p6+p7));
        float dfull = dmine + __shfl_xor_sync(0xffffffffu, dmine, 1);

        float abx  = (t > 0) ? (abv + gxv.y) : gxv.y;
        float preh = hbmine * gam_s;
        float hpn = (t > 0) ? fmaf(fmaf(-sum, gamI, preh), rin, bet_s) : 0.f;
        float nextraw = fmaf(fmaf(-sum, agI, dfull), rin, abx);
        float hb = fmaf(gxv.x, nextraw - hpn, hpn);
        if (t > 0 && !q) Hp[(size_t)(t-1)*S_] = hpn;
        if (!q) hbuf[p ^ 1][hoff] = hb;
        hbmine = hb;

        float s1 = hb, s2 = hb*hb;
#pragma unroll
        for (int off = 16; off > 2; off >>= 1) {
            s1 += __shfl_xor_sync(0xffffffffu, s1, off);
            s2 += __shfl_xor_sync(0xffffffffu, s2, off);
        }
        if ((lane & 0x1D) == 0) red[p ^ 1][2*w + (lane >> 1)] = make_float2(s1, s2);
        __syncthreads();
        p ^= 1;
    }

    {
        const float4* rp = (const float4*)red[p];
        float4 r0 = rp[0], r1 = rp[1], r2 = rp[2], r3 = rp[3];
        float4 r4 = rp[4], r5 = rp[5], r6 = rp[6], r7 = rp[7];
        float sum = (((r0.x + r0.z) + (r1.x + r1.z)) + ((r2.x + r2.z) + (r3.x + r3.z)))
                  + (((r4.x + r4.z) + (r5.x + r5.z)) + ((r6.x + r6.z) + (r7.x + r7.z)));
        float ssq = (((r0.y + r0.w) + (r1.y + r1.w)) + ((r2.y + r2.w) + (r3.y + r3.w)))
                  + (((r4.y + r4.w) + (r5.y + r5.w)) + ((r6.y + r6.w) + (r7.y + r7.w)));
        float mu  = sum * invS;
        float ve  = fmaf(ssq, invS, LN_EPS) - mu*mu;
        float rin = rsqrtf(ve);
        float hpn = fmaf(fmaf(-sum, gamI, hbmine*gam_s), rin, bet_s);
        if (!q) Hp[(size_t)(T_-1)*S_] = hpn;
    }
}

// ---------- outK: hf-split + register double-buffer prefetch (R13, measured 193us) ----------
__global__ __launch_bounds__(128) void outK(
    const float* __restrict__ x, const float* __restrict__ C,
    const float* __restrict__ D, float* __restrict__ out)
{
    __shared__ __align__(16) float Hs[512];
    __shared__ __align__(16) float xsO[256];
    __shared__ __align__(16) float Ysf[4][64];
    __shared__ __align__(16) float Ys2f[4][64];
    __shared__ __align__(16) float ypS[64];

    int tid = threadIdx.x;
    int b = blockIdx.x >> 4, seg = blockIdx.x & 15;
    int o = tid & 63, hf = tid >> 6;
    int w = tid >> 5, lane = tid & 31;

    ull c2[32], d2[16];
#pragma unroll
    for (int k = 0; k < 32; k++)
        c2[k] = pack2(C[o*S_ + hf*64 + 2*k], C[o*S_ + hf*64 + 2*k+1]);
#pragma unroll
    for (int k = 0; k < 16; k++)
        d2[k] = pack2(D[o*I_ + hf*32 + 2*k], D[o*I_ + hf*32 + 2*k+1]);
    float* dsth = hf ? &Ys2f[0][0] : &Ysf[0][0];
    float boS=0.f, boQ=0.f, nrmAcc=0.f, difAcc=0.f, ylastR=0.f;
    int t0 = seg << 7;

    const float* Hb = g_H + (size_t)b*T_*S_;
    const float* xb = x + (size_t)b*T_*I_;

    if (seg > 0) {
        Hs[tid] = Hb[(size_t)(t0-1)*S_ + tid];
        if (tid < 64) xsO[tid] = xb[(size_t)(t0-1)*I_ + tid];
        __syncthreads();
        {
            const ull* hv = (const ull*)(Hs + hf*64);
            const ull* xv = (const ull*)(xsO + hf*32);
            ull a0=0, a1=0;
#pragma unroll
            for (int k = 0; k < 32; k += 2) {
                a0 = ffma2(c2[k], hv[k], a0); a1 = ffma2(c2[k+1], hv[k+1], a1);
            }
#pragma unroll
            for (int k = 0; k < 16; k += 2) {
                a0 = ffma2(d2[k], xv[k], a0); a1 = ffma2(d2[k+1], xv[k+1], a1);
            }
            float u,v,e,f2; unpack2(a0,u,v); unpack2(a1,e,f2);
            dsth[o] = (u+v)+(e+f2);
        }
        __syncthreads();
        if (tid < 64) ylastR = Ysf[0][tid] + Ys2f[0][tid];
    }

    float pH[4], px0, px1;
#pragma unroll
    for (int j = 0; j < 4; j++) pH[j] = Hb[(size_t)(t0 + j)*S_ + tid];
    px0 = xb[(size_t)(t0 +     (tid >> 6))*I_ + o];
    px1 = xb[(size_t)(t0 + 2 + (tid >> 6))*I_ + o];

    for (int g = 0; g < SEGT/4; g++) {
        int tbase = t0 + (g << 2);
        __syncthreads();
        if (tid < 64) ypS[tid] = ylastR;
#pragma unroll
        for (int j = 0; j < 4; j++) Hs[j*128 + tid] = pH[j];
        xsO[tid]       = px0;
        xsO[tid + 128] = px1;
        __syncthreads();

        if (g + 1 < SEGT/4) {
            int tn = tbase + 4;
#pragma unroll
            for (int j = 0; j < 4; j++) pH[j] = Hb[(size_t)(tn + j)*S_ + tid];
            px0 = xb[(size_t)(tn +     (tid >> 6))*I_ + o];
            px1 = xb[(size_t)(tn + 2 + (tid >> 6))*I_ + o];
        }
#pragma unroll
        for (int r = 0; r < 4; r++) {
            const ull* hv = (const ull*)(Hs + r*128 + hf*64);
            const ull* xv = (const ull*)(xsO + r*64 + hf*32);
            ull a0=0, a1=0, a2b=0, a3=0;
#pragma unroll
            for (int k = 0; k < 32; k += 4) {
                a0  = ffma2(c2[k],   hv[k],   a0);
                a1  = ffma2(c2[k+1], hv[k+1], a1);
                a2b = ffma2(c2[k+2], hv[k+2], a2b);
                a3  = ffma2(c2[k+3], hv[k+3], a3);
            }
#pragma unroll
            for (int k = 0; k < 16; k += 4) {
                a0  = ffma2(d2[k],   xv[k],   a0);
                a1  = ffma2(d2[k+1], xv[k+1], a1);
                a2b = ffma2(d2[k+2], xv[k+2], a2b);
                a3  = ffma2(d2[k+3], xv[k+3], a3);
            }
            float u,v,e,f2,m,n,pp,qq;
            unpack2(a0,u,v); unpack2(a1,e,f2); unpack2(a2b,m,n); unpack2(a3,pp,qq);
            dsth[r*64 + o] = ((u+v)+(e+f2)) + ((m+n)+(pp+qq));
        }
        __syncthreads();
#pragma unroll
        for (int rr = 0; rr < 2; rr++) {
            int r = hf + rr*2;
            float y = Ysf[r][o] + Ys2f[r][o];
            Ysf[r][o] = y;
            boS += y; boQ += y*y;
            if (tbase + r == T_-1) out[b*O_ + o] = y;
        }
        __syncthreads();
        {
            float y0 = Ysf[w][lane], y1 = Ysf[w][lane+32];
            float p0, p1;
            if (w == 0) { p0 = ypS[lane]; p1 = ypS[lane+32]; }
            else        { p0 = Ysf[w-1][lane]; p1 = Ysf[w-1][lane+32]; }
            float sn = y0*y0 + y1*y1;
            float d0 = y0 - p0, d1 = y1 - p1;
            float dn = d0*d0 + d1*d1;
#pragma unroll
            for (int off = 16; off > 0; off >>= 1) {
                sn += __shfl_xor_sync(0xffffffffu, sn, off);
                dn += __shfl_xor_sync(0xffffffffu, dn, off);
            }
            if (lane == 0) {
                nrmAcc += sqrtf(sn);
                if (tbase + w > 0) difAcc += sqrtf(dn);
            }
            if (tid < 64) ylastR = Ysf[3][tid];
        }
    }

    if (lane == 0) { atomicAdd(&g_S2, nrmAcc); atomicAdd(&g_S1, difAcc); }
    __syncthreads();
    Hs[tid] = boS;
    __syncthreads();
    if (tid < 64) atomicAdd(&g_boSum[b*O_ + tid], Hs[tid] + Hs[tid+64]);
    __syncthreads();
    Hs[tid] = boQ;
    __syncthreads();
    if (tid < 64) atomicAdd(&g_boSsq[b*O_ + tid], Hs[tid] + Hs[tid+64]);
}

__global__ void finK(float* __restrict__ out)
{
    __shared__ float part[8];
    int tid = threadIdx.x;
    float acc = 0.f;
    for (int idx = tid; idx < B_*O_; idx += 256) {
        float sum = g_boSum[idx], ssq = g_boSsq[idx];
        float var = (ssq - sum*sum*(1.f/T_)) * (1.f/(T_ - 1));
        acc += sqrtf(fmaxf(var, 0.f));
    }
#pragma unroll
    for (int off = 16; off > 0; off >>= 1) acc += __shfl_xor_sync(0xffffffffu, acc, off);
    if ((tid & 31) == 0) part[tid >> 5] = acc;
    __syncthreads();
    if (tid == 0) {
        float tot = 0.f;
#pragma unroll
        for (int k = 0; k < 8; k++) tot += part[k];
        out[4096] = 1.f / (1.f + g_S1 / (float)(B_*(T_-1)));
        out[4097] = g_S2 / (float)(B_*T_);
        out[4098] = g_SA / (float)(B_*S_);
        out[4099] = tot  / (float)(B_*O_);
    }
}

extern "C" void kernel_launch(void* const* d_in, const int* in_sizes, int n_in,
                              void* d_out, int out_size)
{
    const float* x     = (const float*)d_in[0];
    const float* A     = (const float*)d_in[1];
    const float* Bm    = (const float*)d_in[2];
    const float* C     = (const float*)d_in[3];
    const float* D     = (const float*)d_in[4];
    const float* Wsel  = (const float*)d_in[5];
    const float* bsel  = (const float*)d_in[6];
    const float* gamma = (const float*)d_in[7];
    const float* beta  = (const float*)d_in[8];
    float* out = (float*)d_out;

    zeroA<<<16, 256>>>();
    zeroB<<<16, 256>>>();
    gateK<<<B_*8, 128>>>(x, Wsel, bsel, Bm);
    recK<<<B_, 256>>>(A, gamma, beta);      // profiled slot
    outK<<<B_*NSEG, 128>>>(x, C, D, out);
    selFin<<<B_, 128>>>(Wsel, bsel);
    finK<<<1, 256>>>(out);
}